// round 1
// baseline (speedup 1.0000x reference)
#include <cuda_runtime.h>
#include <cstdint>

#define D      512
#define KPROT  1024
#define NMAX   131072

#define TM   64        // rows per CTA in K2
#define TN   64        // cluster tile width in K2
#define DK   256       // D chunk for proto tile
#define RS   513       // rows smem stride (odd -> conflict-free)
#define PS   257       // proto smem stride (odd -> conflict-free)

// ---- device scratch (no allocations allowed) ----
__device__ float g_protoN[KPROT * D];   // normalized prototypes
__device__ float g_sums[KPROT * D];     // per-cluster sums of normalized embeddings
__device__ int   g_counts[KPROT];
__device__ int   g_assign[NMAX];
__device__ float g_invn[NMAX];          // 1/max(||row||, eps)

// =====================================================================
// K1: normalize prototypes (warp per row) + zero sums/counts
// grid: KPROT/8 blocks x 256
// =====================================================================
__global__ void k1_norm_proto(const float* __restrict__ protos) {
    int lane = threadIdx.x & 31;
    int wrow = blockIdx.x * 8 + (threadIdx.x >> 5);
    if (blockIdx.x < 4) g_counts[blockIdx.x * 256 + threadIdx.x] = 0;
    if (wrow >= KPROT) return;

    const float* p = protos + (size_t)wrow * D;
    float v[16];
    float ss = 0.f;
#pragma unroll
    for (int q = 0; q < 16; ++q) { v[q] = p[lane + 32 * q]; ss += v[q] * v[q]; }
#pragma unroll
    for (int o = 16; o; o >>= 1) ss += __shfl_xor_sync(0xffffffffu, ss, o);
    float inv = 1.f / fmaxf(sqrtf(ss), 1e-6f);

    float* dn = g_protoN + (size_t)wrow * D;
    float* dsum = g_sums + (size_t)wrow * D;
#pragma unroll
    for (int q = 0; q < 16; ++q) {
        dn[lane + 32 * q] = v[q] * inv;
        dsum[lane + 32 * q] = 0.f;
    }
}

// =====================================================================
// K2: normalize 64 embedding rows into smem, GEMM vs all 1024 normalized
// prototypes in 64-cluster tiles, fused running argmax per row.
// 256 threads as 16x16: thread (ty,tx) owns rows {i*16+ty}, cols {j*16+tx}.
// =====================================================================
__global__ void k2_assign(const float* __restrict__ emb, int n) {
    extern __shared__ float smem[];
    float* rows_s  = smem;                 // TM * RS
    float* proto_s = smem + TM * RS;       // TN * PS

    const int tid  = threadIdx.x;
    const int lane = tid & 31;
    const int warp = tid >> 5;
    const int row0 = blockIdx.x * TM;

    // ---- Phase A: load + normalize 64 rows (warp per row, 8 rows/warp) ----
#pragma unroll
    for (int rr = 0; rr < 8; ++rr) {
        int r = warp * 8 + rr;
        int grow = row0 + r;
        if (grow < n) {
            const float* src = emb + (size_t)grow * D;
            float v[16];
            float ss = 0.f;
#pragma unroll
            for (int q = 0; q < 16; ++q) { v[q] = src[lane + 32 * q]; ss += v[q] * v[q]; }
#pragma unroll
            for (int o = 16; o; o >>= 1) ss += __shfl_xor_sync(0xffffffffu, ss, o);
            float inv = 1.f / fmaxf(sqrtf(ss), 1e-6f);
#pragma unroll
            for (int q = 0; q < 16; ++q) rows_s[r * RS + lane + 32 * q] = v[q] * inv;
            if (lane == 0) g_invn[grow] = inv;
        } else {
#pragma unroll
            for (int q = 0; q < 16; ++q) rows_s[r * RS + lane + 32 * q] = 0.f;
        }
    }
    __syncthreads();

    const int ty = tid >> 4;
    const int tx = tid & 15;

    float best_v[4];
    int   best_i[4];
#pragma unroll
    for (int i = 0; i < 4; ++i) { best_v[i] = -__int_as_float(0x7f800000); best_i[i] = 0; }

    for (int ct = 0; ct < KPROT / TN; ++ct) {
        float acc[4][4];
#pragma unroll
        for (int i = 0; i < 4; ++i)
#pragma unroll
            for (int j = 0; j < 4; ++j) acc[i][j] = 0.f;

        for (int dk = 0; dk < D / DK; ++dk) {
            // load proto tile [TN][DK] (coalesced over d)
            for (int idx = tid; idx < TN * DK; idx += 256) {
                int cl = idx >> 8;          // idx / DK
                int d  = idx & (DK - 1);
                proto_s[cl * PS + d] = g_protoN[(size_t)(ct * TN + cl) * D + dk * DK + d];
            }
            __syncthreads();

            const float* rbase = rows_s + dk * DK;
#pragma unroll 4
            for (int d = 0; d < DK; ++d) {
                float a0 = rbase[(0 * 16 + ty) * RS + d];
                float a1 = rbase[(1 * 16 + ty) * RS + d];
                float a2 = rbase[(2 * 16 + ty) * RS + d];
                float a3 = rbase[(3 * 16 + ty) * RS + d];
                float b0 = proto_s[(0 * 16 + tx) * PS + d];
                float b1 = proto_s[(1 * 16 + tx) * PS + d];
                float b2 = proto_s[(2 * 16 + tx) * PS + d];
                float b3 = proto_s[(3 * 16 + tx) * PS + d];
                acc[0][0] += a0 * b0; acc[0][1] += a0 * b1; acc[0][2] += a0 * b2; acc[0][3] += a0 * b3;
                acc[1][0] += a1 * b0; acc[1][1] += a1 * b1; acc[1][2] += a1 * b2; acc[1][3] += a1 * b3;
                acc[2][0] += a2 * b0; acc[2][1] += a2 * b1; acc[2][2] += a2 * b2; acc[2][3] += a2 * b3;
                acc[3][0] += a3 * b0; acc[3][1] += a3 * b1; acc[3][2] += a3 * b2; acc[3][3] += a3 * b3;
            }
            __syncthreads();
        }

        // ---- tile argmax epilogue (registers + shuffles only) ----
#pragma unroll
        for (int i = 0; i < 4; ++i) {
            float bv = acc[i][0];
            int   bi = ct * TN + 0 * 16 + tx;
#pragma unroll
            for (int j = 1; j < 4; ++j) {
                int idx = ct * TN + j * 16 + tx;
                if (acc[i][j] > bv) { bv = acc[i][j]; bi = idx; }
            }
            // reduce across the 16 tx lanes of this half-warp segment
#pragma unroll
            for (int off = 8; off; off >>= 1) {
                float ov = __shfl_down_sync(0xffffffffu, bv, off, 16);
                int   oi = __shfl_down_sync(0xffffffffu, bi, off, 16);
                if (ov > bv || (ov == bv && oi < bi)) { bv = ov; bi = oi; }
            }
            bv = __shfl_sync(0xffffffffu, bv, 0, 16);
            bi = __shfl_sync(0xffffffffu, bi, 0, 16);
            if (bv > best_v[i] || (bv == best_v[i] && bi < best_i[i])) {
                best_v[i] = bv; best_i[i] = bi;
            }
        }
    }

    if (tx == 0) {
#pragma unroll
        for (int i = 0; i < 4; ++i) {
            int grow = row0 + i * 16 + ty;
            if (grow < n) g_assign[grow] = best_i[i];
        }
    }
}

// =====================================================================
// K3: segment accumulation. warp per row; float4 vector atomics into
// g_sums (addresses spread over 512K locations -> high L2-atom parallelism)
// grid: n/8 blocks x 256
// =====================================================================
__global__ void k3_accum(const float* __restrict__ emb, int n) {
    int lane = threadIdx.x & 31;
    int row  = blockIdx.x * 8 + (threadIdx.x >> 5);
    if (row >= n) return;

    int   k   = g_assign[row];
    float inv = g_invn[row];
    const float4* src = (const float4*)(emb + (size_t)row * D);
    float4* dst = (float4*)(g_sums + (size_t)k * D);
#pragma unroll
    for (int q = 0; q < 4; ++q) {
        float4 v = src[q * 32 + lane];
        v.x *= inv; v.y *= inv; v.z *= inv; v.w *= inv;
#if __CUDA_ARCH__ >= 900
        atomicAdd(&dst[q * 32 + lane], v);
#else
        float* d = (float*)&dst[q * 32 + lane];
        atomicAdd(d + 0, v.x); atomicAdd(d + 1, v.y);
        atomicAdd(d + 2, v.z); atomicAdd(d + 3, v.w);
#endif
    }
    if (lane == 0) atomicAdd(&g_counts[k], 1);
}

// =====================================================================
// K4: EMA + renormalize + where(has). warp per prototype row.
// grid: KPROT/8 blocks x 256
// =====================================================================
__global__ void k4_final(const float* __restrict__ protos, float* __restrict__ out) {
    int lane = threadIdx.x & 31;
    int k    = blockIdx.x * 8 + (threadIdx.x >> 5);
    if (k >= KPROT) return;

    int   cnt = g_counts[k];
    float cf  = fmaxf((float)cnt, 1.f);
    float pv[16], uv[16];
    float ss = 0.f;
#pragma unroll
    for (int q = 0; q < 16; ++q) {
        pv[q] = protos[(size_t)k * D + lane + 32 * q];
        float m = g_sums[(size_t)k * D + lane + 32 * q] / cf;
        uv[q] = 0.9f * pv[q] + 0.1f * m;
        ss += uv[q] * uv[q];
    }
#pragma unroll
    for (int o = 16; o; o >>= 1) ss += __shfl_xor_sync(0xffffffffu, ss, o);
    float inv = 1.f / fmaxf(sqrtf(ss), 1e-6f);
#pragma unroll
    for (int q = 0; q < 16; ++q) {
        out[(size_t)k * D + lane + 32 * q] = (cnt > 0) ? uv[q] * inv : pv[q];
    }
}

// =====================================================================
extern "C" void kernel_launch(void* const* d_in, const int* in_sizes, int n_in,
                              void* d_out, int out_size) {
    const float* emb    = (const float*)d_in[0];
    const float* protos = (const float*)d_in[1];
    float* out = (float*)d_out;
    int n = in_sizes[0] / D;   // 131072

    size_t smem2 = (size_t)(TM * RS + TN * PS) * sizeof(float);  // ~197 KB
    cudaFuncSetAttribute(k2_assign, cudaFuncAttributeMaxDynamicSharedMemorySize, (int)smem2);

    k1_norm_proto<<<KPROT / 8, 256>>>(protos);
    k2_assign<<<n / TM, 256, smem2>>>(emb, n);
    k3_accum<<<n / 8, 256>>>(emb, n);
    k4_final<<<KPROT / 8, 256>>>(protos, out);
}

// round 3
// speedup vs baseline: 9.0461x; 9.0461x over previous
#include <cuda_runtime.h>
#include <cuda_bf16.h>
#include <cstdint>

#define D      512
#define KPROT  1024
#define NMAX   131072

// ---------------- device scratch ----------------
__device__ float         g_protoN [KPROT * D];     // normalized prototypes fp32 (rescoring)
__device__ __nv_bfloat16 g_protoNh[KPROT * D];     // normalized prototypes bf16 (GEMM)
__device__ __nv_bfloat16 g_embNh  [NMAX * D];      // normalized embeddings bf16 (GEMM)
__device__ float         g_sums   [KPROT * D];
__device__ int           g_counts [KPROT];
__device__ float         g_invn   [NMAX];
__device__ int           g_cand   [NMAX * 2];      // top-2 candidate protos per row

// ---------------- helpers ----------------
__device__ __forceinline__ uint32_t smem_u32(const void* p) {
    uint32_t a;
    asm("{ .reg .u64 t; cvta.to.shared.u64 t, %1; cvt.u32.u64 %0, t; }" : "=r"(a) : "l"(p));
    return a;
}
#define SWZ(x) ((x) ^ (((x) >> 3) & 0x70))

#define CP_ASYNC16(dst, src) \
    asm volatile("cp.async.cg.shared.global [%0], [%1], 16;" :: "r"(dst), "l"(src))
#define CP_COMMIT() asm volatile("cp.async.commit_group;")
#define CP_WAIT(n)  asm volatile("cp.async.wait_group %0;" :: "n"(n))

__device__ __forceinline__ void ldsm_x4(uint32_t a[4], uint32_t addr) {
    asm volatile("ldmatrix.sync.aligned.m8n8.x4.shared.b16 {%0,%1,%2,%3}, [%4];"
        : "=r"(a[0]), "=r"(a[1]), "=r"(a[2]), "=r"(a[3]) : "r"(addr));
}
__device__ __forceinline__ void ldsm_x2(uint32_t b[2], uint32_t addr) {
    asm volatile("ldmatrix.sync.aligned.m8n8.x2.shared.b16 {%0,%1}, [%2];"
        : "=r"(b[0]), "=r"(b[1]) : "r"(addr));
}
__device__ __forceinline__ void mma16816(float c[4], const uint32_t a[4], const uint32_t b[2]) {
    asm volatile(
        "mma.sync.aligned.m16n8k16.row.col.f32.bf16.bf16.f32 "
        "{%0,%1,%2,%3},{%4,%5,%6,%7},{%8,%9},{%0,%1,%2,%3};"
        : "+f"(c[0]), "+f"(c[1]), "+f"(c[2]), "+f"(c[3])
        : "r"(a[0]), "r"(a[1]), "r"(a[2]), "r"(a[3]), "r"(b[0]), "r"(b[1]));
}

// =====================================================================
// K0: normalize embeddings -> bf16 (g_embNh) + 1/norm (g_invn)
// warp per row; grid n/8 x 256
// =====================================================================
__global__ void k0_norm_emb(const float* __restrict__ emb, int n) {
    int lane = threadIdx.x & 31;
    int row  = blockIdx.x * 8 + (threadIdx.x >> 5);
    if (row >= n) return;

    const float4* src = (const float4*)(emb + (size_t)row * D);
    float4 v[4];
    float ss = 0.f;
    #pragma unroll
    for (int q = 0; q < 4; ++q) {
        v[q] = src[q * 32 + lane];
        ss += v[q].x * v[q].x + v[q].y * v[q].y + v[q].z * v[q].z + v[q].w * v[q].w;
    }
    #pragma unroll
    for (int o = 16; o; o >>= 1) ss += __shfl_xor_sync(0xffffffffu, ss, o);
    float inv = 1.f / fmaxf(sqrtf(ss), 1e-6f);
    if (lane == 0) g_invn[row] = inv;

    uint2* dst = (uint2*)(g_embNh + (size_t)row * D);
    #pragma unroll
    for (int q = 0; q < 4; ++q) {
        __nv_bfloat162 b0 = __floats2bfloat162_rn(v[q].x * inv, v[q].y * inv);
        __nv_bfloat162 b1 = __floats2bfloat162_rn(v[q].z * inv, v[q].w * inv);
        dst[q * 32 + lane] = make_uint2(*(uint32_t*)&b0, *(uint32_t*)&b1);
    }
}

// =====================================================================
// K1: normalize prototypes -> fp32 + bf16; zero sums/counts
// =====================================================================
__global__ void k1_norm_proto(const float* __restrict__ protos) {
    int lane = threadIdx.x & 31;
    int row  = blockIdx.x * 8 + (threadIdx.x >> 5);

    if (blockIdx.x < 4) g_counts[blockIdx.x * 256 + threadIdx.x] = 0;
    {
        float4* s4 = (float4*)g_sums;
        int t = blockIdx.x * 256 + threadIdx.x;
        #pragma unroll
        for (int q = 0; q < 4; ++q) s4[q * 32768 + t] = make_float4(0.f, 0.f, 0.f, 0.f);
    }

    const float4* src = (const float4*)(protos + (size_t)row * D);
    float4 v[4];
    float ss = 0.f;
    #pragma unroll
    for (int q = 0; q < 4; ++q) {
        v[q] = src[q * 32 + lane];
        ss += v[q].x * v[q].x + v[q].y * v[q].y + v[q].z * v[q].z + v[q].w * v[q].w;
    }
    #pragma unroll
    for (int o = 16; o; o >>= 1) ss += __shfl_xor_sync(0xffffffffu, ss, o);
    float inv = 1.f / fmaxf(sqrtf(ss), 1e-6f);

    float4* dstf = (float4*)(g_protoN + (size_t)row * D);
    uint2*  dsth = (uint2*)(g_protoNh + (size_t)row * D);
    #pragma unroll
    for (int q = 0; q < 4; ++q) {
        float4 w = make_float4(v[q].x * inv, v[q].y * inv, v[q].z * inv, v[q].w * inv);
        dstf[q * 32 + lane] = w;
        __nv_bfloat162 b0 = __floats2bfloat162_rn(w.x, w.y);
        __nv_bfloat162 b1 = __floats2bfloat162_rn(w.z, w.w);
        dsth[q * 32 + lane] = make_uint2(*(uint32_t*)&b0, *(uint32_t*)&b1);
    }
}

// =====================================================================
// K2: bf16 mma.sync GEMM [128 rows x 1024 protos x 512] per CTA,
// fused per-row top-2. A resident in SMEM (128KB, SW128 swizzled,
// 8 k-chunks of 128x64), B double-buffered 16KB k-chunks via cp.async.
// 8 warps = 2(M) x 4(N); warp tile 64x32; mma m16n8k16.
// =====================================================================
#define FOLD(slot, val, col) do { \
    float _v = (val); int _c = (col); \
    if (_v > tv1[slot]) { tv2[slot] = tv1[slot]; ti2[slot] = ti1[slot]; tv1[slot] = _v; ti1[slot] = _c; } \
    else if (_v > tv2[slot]) { tv2[slot] = _v; ti2[slot] = _c; } \
} while (0)

__global__ void __launch_bounds__(256, 1) k2_mma(int n) {
    extern __shared__ char smem[];
    const uint32_t sbA = smem_u32(smem);
    const uint32_t sbB = sbA + 131072;

    const int tid  = threadIdx.x;
    const int lane = tid & 31;
    const int wid  = tid >> 5;
    const int wm   = wid >> 2;   // 0..1
    const int wn   = wid & 3;    // 0..3
    const int row0 = blockIdx.x * 128;

    // ---- issue A loads (full 128x512 bf16) + B(pt0,kc0) into stage 0 ----
    {
        const char* srcA = (const char*)(g_embNh + (size_t)row0 * D);
        #pragma unroll
        for (int i = 0; i < 32; ++i) {
            int v = tid + i * 256;                 // 0..8191
            int r = v >> 6;                        // row 0..127
            int slot = v & 63;                     // 16B slot in row
            uint32_t dst = sbA + (uint32_t)(slot >> 3) * 16384u
                         + SWZ((uint32_t)(r * 128 + (slot & 7) * 16));
            CP_ASYNC16(dst, srcA + (size_t)r * 1024 + slot * 16);
        }
        const char* srcB = (const char*)g_protoNh;
        #pragma unroll
        for (int i = 0; i < 4; ++i) {
            int v = tid + i * 256;                 // 0..1023
            int pr = v >> 3, slot = v & 7;
            CP_ASYNC16(sbB + SWZ((uint32_t)(pr * 128 + slot * 16)),
                       srcB + (size_t)pr * 1024 + slot * 16);
        }
        CP_COMMIT();
    }

    float acc[4][4][4];
    float tv1[8], tv2[8];
    int   ti1[8], ti2[8];
    #pragma unroll
    for (int s = 0; s < 8; ++s) { tv1[s] = -3.4e38f; tv2[s] = -3.4e38f; ti1[s] = 0; ti2[s] = 0; }

    // ldmatrix base byte offsets + swizzle XOR values
    uint32_t rbA[4], xA[4], rbB[4], xB[4];
    {
        int l2 = lane & 15;
        #pragma unroll
        for (int mf = 0; mf < 4; ++mf) {
            uint32_t rb = (uint32_t)((wm * 64 + mf * 16 + (lane & 15)) * 128 + (lane >> 4) * 16);
            rbA[mf] = rb; xA[mf] = (rb >> 3) & 0x70;
        }
        #pragma unroll
        for (int nf = 0; nf < 4; ++nf) {
            uint32_t rb = (uint32_t)((wn * 32 + nf * 8 + (l2 & 7)) * 128 + (l2 >> 3) * 16);
            rbB[nf] = rb; xB[nf] = (rb >> 3) & 0x70;
        }
    }

    for (int idx = 0; idx < 64; ++idx) {
        const int pt  = idx >> 3;
        const int kc  = idx & 7;
        const int stg = idx & 1;

        if (idx + 1 < 64) {
            const int pt2 = (idx + 1) >> 3, kc2 = (idx + 1) & 7;
            const char* srcB = (const char*)(g_protoNh + (size_t)(pt2 * 128) * D + kc2 * 64);
            uint32_t base = sbB + (uint32_t)((idx + 1) & 1) * 16384u;
            #pragma unroll
            for (int i = 0; i < 4; ++i) {
                int v = tid + i * 256;
                int pr = v >> 3, slot = v & 7;
                CP_ASYNC16(base + SWZ((uint32_t)(pr * 128 + slot * 16)),
                           srcB + (size_t)pr * 1024 + slot * 16);
            }
            CP_COMMIT();
            CP_WAIT(1);
        } else {
            CP_WAIT(0);
        }
        __syncthreads();

        if (kc == 0) {
            #pragma unroll
            for (int mf = 0; mf < 4; ++mf)
                #pragma unroll
                for (int nf = 0; nf < 4; ++nf)
                    #pragma unroll
                    for (int q = 0; q < 4; ++q) acc[mf][nf][q] = 0.f;
        }

        const uint32_t aBase = sbA + (uint32_t)kc * 16384u;
        const uint32_t bBase = sbB + (uint32_t)stg * 16384u;
        #pragma unroll
        for (int ks = 0; ks < 4; ++ks) {
            uint32_t af[4][4], bf[4][2];
            #pragma unroll
            for (int mf = 0; mf < 4; ++mf)
                ldsm_x4(af[mf], aBase + ((rbA[mf] + ks * 32) ^ xA[mf]));
            #pragma unroll
            for (int nf = 0; nf < 4; ++nf)
                ldsm_x2(bf[nf], bBase + ((rbB[nf] + ks * 32) ^ xB[nf]));
            #pragma unroll
            for (int mf = 0; mf < 4; ++mf)
                #pragma unroll
                for (int nf = 0; nf < 4; ++nf)
                    mma16816(acc[mf][nf], af[mf], bf[nf]);
        }

        if (kc == 7) {
            #pragma unroll
            for (int mf = 0; mf < 4; ++mf) {
                #pragma unroll
                for (int nf = 0; nf < 4; ++nf) {
                    int col = pt * 128 + wn * 32 + nf * 8 + (lane & 3) * 2;
                    FOLD(mf * 2 + 0, acc[mf][nf][0], col);
                    FOLD(mf * 2 + 0, acc[mf][nf][1], col + 1);
                    FOLD(mf * 2 + 1, acc[mf][nf][2], col);
                    FOLD(mf * 2 + 1, acc[mf][nf][3], col + 1);
                }
            }
        }
        __syncthreads();
    }

    // ---- quad reduce (lanes with same lane/4 share rows, differ in cols) ----
    #pragma unroll
    for (int s = 0; s < 8; ++s) {
        #pragma unroll
        for (int off = 1; off <= 2; off <<= 1) {
            float ov1 = __shfl_xor_sync(0xffffffffu, tv1[s], off);
            int   oi1 = __shfl_xor_sync(0xffffffffu, ti1[s], off);
            float ov2 = __shfl_xor_sync(0xffffffffu, tv2[s], off);
            int   oi2 = __shfl_xor_sync(0xffffffffu, ti2[s], off);
            bool alead = (tv1[s] > ov1) || (tv1[s] == ov1 && ti1[s] < oi1);
            float nv1 = alead ? tv1[s] : ov1;  int ni1 = alead ? ti1[s] : oi1;
            float cv  = alead ? ov1 : tv1[s];  int ci  = alead ? oi1 : ti1[s];
            float sv  = alead ? tv2[s] : ov2;  int si  = alead ? ti2[s] : oi2;
            bool slead = (sv > cv) || (sv == cv && si < ci);
            tv1[s] = nv1; ti1[s] = ni1;
            tv2[s] = slead ? sv : cv; ti2[s] = slead ? si : ci;
        }
    }
    __syncthreads();   // done with B smem; reuse for cross-warp merge

    float4* buf = (float4*)(smem + 131072);
    if ((lane & 3) == 0) {
        #pragma unroll
        for (int mf = 0; mf < 4; ++mf)
            #pragma unroll
            for (int h = 0; h < 2; ++h) {
                int r = wm * 64 + mf * 16 + (lane >> 2) + h * 8;
                int s = mf * 2 + h;
                buf[wn * 128 + r] = make_float4(tv1[s], __int_as_float(ti1[s]),
                                                tv2[s], __int_as_float(ti2[s]));
            }
    }
    __syncthreads();

    if (tid < 128) {
        float4 m = buf[tid];
        float v1 = m.x; int i1 = __float_as_int(m.y);
        float v2 = m.z; int i2 = __float_as_int(m.w);
        #pragma unroll
        for (int w = 1; w < 4; ++w) {
            float4 o = buf[w * 128 + tid];
            float ov1 = o.x; int oi1 = __float_as_int(o.y);
            float ov2 = o.z; int oi2 = __float_as_int(o.w);
            bool alead = (v1 > ov1) || (v1 == ov1 && i1 < oi1);
            float nv1 = alead ? v1 : ov1;  int ni1 = alead ? i1 : oi1;
            float cv  = alead ? ov1 : v1;  int ci  = alead ? oi1 : i1;
            float sv  = alead ? v2 : ov2;  int si  = alead ? i2 : oi2;
            bool slead = (sv > cv) || (sv == cv && si < ci);
            v1 = nv1; i1 = ni1;
            v2 = slead ? sv : cv; i2 = slead ? si : ci;
        }
        int grow = row0 + tid;
        if (grow < n) {
            g_cand[grow * 2 + 0] = i1;
            g_cand[grow * 2 + 1] = i2;
        }
    }
}

// =====================================================================
// K3: fp32 rescoring of top-2 candidates + segment accumulation.
// =====================================================================
__global__ void k3_rescore_accum(const float* __restrict__ emb, int n) {
    int lane = threadIdx.x & 31;
    int row  = blockIdx.x * 8 + (threadIdx.x >> 5);
    if (row >= n) return;

    int i1 = g_cand[row * 2 + 0];
    int i2 = g_cand[row * 2 + 1];
    float inv = g_invn[row];

    const float4* e4 = (const float4*)(emb + (size_t)row * D);
    const float4* p1 = (const float4*)(g_protoN + (size_t)i1 * D);
    const float4* p2 = (const float4*)(g_protoN + (size_t)i2 * D);

    float4 ev[4];
    float s1 = 0.f, s2 = 0.f;
    #pragma unroll
    for (int q = 0; q < 4; ++q) {
        ev[q] = e4[q * 32 + lane];
        float4 a = p1[q * 32 + lane];
        float4 b = p2[q * 32 + lane];
        s1 += ev[q].x * a.x + ev[q].y * a.y + ev[q].z * a.z + ev[q].w * a.w;
        s2 += ev[q].x * b.x + ev[q].y * b.y + ev[q].z * b.z + ev[q].w * b.w;
    }
    #pragma unroll
    for (int o = 16; o; o >>= 1) {
        s1 += __shfl_xor_sync(0xffffffffu, s1, o);
        s2 += __shfl_xor_sync(0xffffffffu, s2, o);
    }
    int k = (s2 > s1 || (s2 == s1 && i2 < i1)) ? i2 : i1;

    float4* dst = (float4*)(g_sums + (size_t)k * D);
    #pragma unroll
    for (int q = 0; q < 4; ++q) {
        float4 v = ev[q];
        v.x *= inv; v.y *= inv; v.z *= inv; v.w *= inv;
        atomicAdd(&dst[q * 32 + lane], v);
    }
    if (lane == 0) atomicAdd(&g_counts[k], 1);
}

// =====================================================================
// K4: EMA + renormalize + where(has)
// =====================================================================
__global__ void k4_final(const float* __restrict__ protos, float* __restrict__ out) {
    int lane = threadIdx.x & 31;
    int k    = blockIdx.x * 8 + (threadIdx.x >> 5);
    if (k >= KPROT) return;

    int   cnt = g_counts[k];
    float cf  = fmaxf((float)cnt, 1.f);
    float pv[16], uv[16];
    float ss = 0.f;
    #pragma unroll
    for (int q = 0; q < 16; ++q) {
        pv[q] = protos[(size_t)k * D + lane + 32 * q];
        float m = g_sums[(size_t)k * D + lane + 32 * q] / cf;
        uv[q] = 0.9f * pv[q] + 0.1f * m;
        ss += uv[q] * uv[q];
    }
    #pragma unroll
    for (int o = 16; o; o >>= 1) ss += __shfl_xor_sync(0xffffffffu, ss, o);
    float inv = 1.f / fmaxf(sqrtf(ss), 1e-6f);
    #pragma unroll
    for (int q = 0; q < 16; ++q) {
        out[(size_t)k * D + lane + 32 * q] = (cnt > 0) ? uv[q] * inv : pv[q];
    }
}

// =====================================================================
extern "C" void kernel_launch(void* const* d_in, const int* in_sizes, int n_in,
                              void* d_out, int out_size) {
    const float* emb    = (const float*)d_in[0];
    const float* protos = (const float*)d_in[1];
    float* out = (float*)d_out;
    int n = in_sizes[0] / D;   // 131072

    const int smem2 = 131072 + 2 * 16384;  // 160 KB
    cudaFuncSetAttribute(k2_mma, cudaFuncAttributeMaxDynamicSharedMemorySize, smem2);

    k1_norm_proto<<<KPROT / 8, 256>>>(protos);
    k0_norm_emb<<<(n + 7) / 8, 256>>>(emb, n);
    k2_mma<<<(n + 127) / 128, 256, smem2>>>(n);
    k3_rescore_accum<<<(n + 7) / 8, 256>>>(emb, n);
    k4_final<<<KPROT / 8, 256>>>(protos, out);
}

// round 4
// speedup vs baseline: 9.1272x; 1.0090x over previous
#include <cuda_runtime.h>
#include <cuda_bf16.h>
#include <cstdint>

#define D      512
#define KPROT  1024
#define NMAX   131072

// ---------------- device scratch ----------------
__device__ float         g_protoN [KPROT * D];     // normalized prototypes fp32 (rescoring)
__device__ __nv_bfloat16 g_protoNh[KPROT * D];     // normalized prototypes bf16 (GEMM)
__device__ float         g_sums   [KPROT * D];
__device__ int           g_counts [KPROT];
__device__ float         g_invn   [NMAX];
__device__ int           g_cand   [NMAX * 2];      // top-2 candidate protos per row

// ---------------- helpers ----------------
__device__ __forceinline__ uint32_t smem_u32(const void* p) {
    uint32_t a;
    asm("{ .reg .u64 t; cvta.to.shared.u64 t, %1; cvt.u32.u64 %0, t; }" : "=r"(a) : "l"(p));
    return a;
}
#define SWZ(x) ((x) ^ (((x) >> 3) & 0x70))

#define CP_ASYNC16(dst, src) \
    asm volatile("cp.async.cg.shared.global [%0], [%1], 16;" :: "r"(dst), "l"(src))
#define CP_COMMIT() asm volatile("cp.async.commit_group;")
#define CP_WAIT(n)  asm volatile("cp.async.wait_group %0;" :: "n"(n))

__device__ __forceinline__ void ldsm_x4(uint32_t a[4], uint32_t addr) {
    asm volatile("ldmatrix.sync.aligned.m8n8.x4.shared.b16 {%0,%1,%2,%3}, [%4];"
        : "=r"(a[0]), "=r"(a[1]), "=r"(a[2]), "=r"(a[3]) : "r"(addr));
}
__device__ __forceinline__ void ldsm_x2(uint32_t b[2], uint32_t addr) {
    asm volatile("ldmatrix.sync.aligned.m8n8.x2.shared.b16 {%0,%1}, [%2];"
        : "=r"(b[0]), "=r"(b[1]) : "r"(addr));
}
__device__ __forceinline__ void mma16816(float c[4], const uint32_t a[4], const uint32_t b[2]) {
    asm volatile(
        "mma.sync.aligned.m16n8k16.row.col.f32.bf16.bf16.f32 "
        "{%0,%1,%2,%3},{%4,%5,%6,%7},{%8,%9},{%0,%1,%2,%3};"
        : "+f"(c[0]), "+f"(c[1]), "+f"(c[2]), "+f"(c[3])
        : "r"(a[0]), "r"(a[1]), "r"(a[2]), "r"(a[3]), "r"(b[0]), "r"(b[1]));
}

// =====================================================================
// K1: normalize prototypes -> fp32 + bf16; zero sums/counts
// =====================================================================
__global__ void k1_norm_proto(const float* __restrict__ protos) {
    int lane = threadIdx.x & 31;
    int row  = blockIdx.x * 8 + (threadIdx.x >> 5);

    if (blockIdx.x < 4) g_counts[blockIdx.x * 256 + threadIdx.x] = 0;
    {
        float4* s4 = (float4*)g_sums;
        int t = blockIdx.x * 256 + threadIdx.x;
        #pragma unroll
        for (int q = 0; q < 4; ++q) s4[q * 32768 + t] = make_float4(0.f, 0.f, 0.f, 0.f);
    }

    const float4* src = (const float4*)(protos + (size_t)row * D);
    float4 v[4];
    float ss = 0.f;
    #pragma unroll
    for (int q = 0; q < 4; ++q) {
        v[q] = src[q * 32 + lane];
        ss += v[q].x * v[q].x + v[q].y * v[q].y + v[q].z * v[q].z + v[q].w * v[q].w;
    }
    #pragma unroll
    for (int o = 16; o; o >>= 1) ss += __shfl_xor_sync(0xffffffffu, ss, o);
    float inv = 1.f / fmaxf(sqrtf(ss), 1e-6f);

    float4* dstf = (float4*)(g_protoN + (size_t)row * D);
    uint2*  dsth = (uint2*)(g_protoNh + (size_t)row * D);
    #pragma unroll
    for (int q = 0; q < 4; ++q) {
        float4 w = make_float4(v[q].x * inv, v[q].y * inv, v[q].z * inv, v[q].w * inv);
        dstf[q * 32 + lane] = w;
        __nv_bfloat162 b0 = __floats2bfloat162_rn(w.x, w.y);
        __nv_bfloat162 b1 = __floats2bfloat162_rn(w.z, w.w);
        dsth[q * 32 + lane] = make_uint2(*(uint32_t*)&b0, *(uint32_t*)&b1);
    }
}

// =====================================================================
// K2: fused normalize + bf16 mma.sync GEMM [128 x 1024 x 512] per CTA
// + per-row top-2 candidates.
// A: raw fp32 rows loaded to registers, normalized, stored bf16 into
//    SW128-swizzled SMEM (128 KB, resident).
// B: 4-stage 16 KB cp.async ring, distance-2 prefetch, 1 barrier/tile.
// 8 warps = 2(M) x 4(N); warp tile 64x32; mma m16n8k16.
// =====================================================================
#define FOLD(slot, val, col) do { \
    float _v = (val); int _c = (col); \
    if (_v > tv1[slot]) { tv2[slot] = tv1[slot]; ti2[slot] = ti1[slot]; tv1[slot] = _v; ti1[slot] = _c; } \
    else if (_v > tv2[slot]) { tv2[slot] = _v; ti2[slot] = _c; } \
} while (0)

__global__ void __launch_bounds__(256, 1) k2_mma(const float* __restrict__ emb, int n) {
    extern __shared__ char smem[];
    const uint32_t sbA = smem_u32(smem);
    const uint32_t sbB = sbA + 131072;

    const int tid  = threadIdx.x;
    const int lane = tid & 31;
    const int wid  = tid >> 5;
    const int wm   = wid >> 2;   // 0..1
    const int wn   = wid & 3;    // 0..3
    const int row0 = blockIdx.x * 128;

    // ---- issue B stage 0 and 1 (tiles idx=0,1) ----
    {
        const char* srcB0 = (const char*)g_protoNh;                   // pt=0,kc=0
        #pragma unroll
        for (int i = 0; i < 4; ++i) {
            int v = tid + i * 256;
            int pr = v >> 3, slot = v & 7;
            CP_ASYNC16(sbB + SWZ((uint32_t)(pr * 128 + slot * 16)),
                       srcB0 + (size_t)pr * 1024 + slot * 16);
        }
        CP_COMMIT();
        const char* srcB1 = (const char*)g_protoNh + 128;             // pt=0,kc=1 (64 bf16 = 128B)
        #pragma unroll
        for (int i = 0; i < 4; ++i) {
            int v = tid + i * 256;
            int pr = v >> 3, slot = v & 7;
            CP_ASYNC16(sbB + 16384u + SWZ((uint32_t)(pr * 128 + slot * 16)),
                       srcB1 + (size_t)pr * 1024 + slot * 16);
        }
        CP_COMMIT();
    }

    // ---- A phase: load raw fp32, normalize, convert to bf16 smem ----
    // warp per row, 16 rows per warp. Lane l owns floats [16l, 16l+16).
    #pragma unroll 1
    for (int rr = 0; rr < 16; ++rr) {
        int r = wid * 16 + rr;
        int grow = row0 + r;
        const float4* src = (const float4*)(emb + (size_t)grow * D);
        float4 v[4];
        float ss = 0.f;
        if (grow < n) {
            #pragma unroll
            for (int q = 0; q < 4; ++q) {
                v[q] = src[lane * 4 + q];
                ss += v[q].x * v[q].x + v[q].y * v[q].y + v[q].z * v[q].z + v[q].w * v[q].w;
            }
        } else {
            #pragma unroll
            for (int q = 0; q < 4; ++q) v[q] = make_float4(0.f, 0.f, 0.f, 0.f);
        }
        #pragma unroll
        for (int o = 16; o; o >>= 1) ss += __shfl_xor_sync(0xffffffffu, ss, o);
        float inv = 1.f / fmaxf(sqrtf(ss), 1e-6f);
        if (lane == 0 && grow < n) g_invn[grow] = inv;

        uint32_t hb[8];
        #pragma unroll
        for (int q = 0; q < 4; ++q) {
            __nv_bfloat162 b0 = __floats2bfloat162_rn(v[q].x * inv, v[q].y * inv);
            __nv_bfloat162 b1 = __floats2bfloat162_rn(v[q].z * inv, v[q].w * inv);
            hb[q * 2 + 0] = *(uint32_t*)&b0;
            hb[q * 2 + 1] = *(uint32_t*)&b1;
        }
        // slots 2*lane and 2*lane+1 of row r
        #pragma unroll
        for (int h = 0; h < 2; ++h) {
            int s = lane * 2 + h;
            uint32_t dst = sbA + (uint32_t)(s >> 3) * 16384u
                         + SWZ((uint32_t)(r * 128 + (s & 7) * 16));
            *(uint4*)(uintptr_t)(smem + (dst - sbA)) =
                make_uint4(hb[h * 4 + 0], hb[h * 4 + 1], hb[h * 4 + 2], hb[h * 4 + 3]);
        }
    }

    float acc[4][4][4];
    float tv1[8], tv2[8];
    int   ti1[8], ti2[8];
    #pragma unroll
    for (int s = 0; s < 8; ++s) { tv1[s] = -3.4e38f; tv2[s] = -3.4e38f; ti1[s] = 0; ti2[s] = 0; }

    // ldmatrix base byte offsets + swizzle XOR values
    uint32_t rbA[4], xA[4], rbB[4], xB[4];
    {
        int l2 = lane & 15;
        #pragma unroll
        for (int mf = 0; mf < 4; ++mf) {
            uint32_t rb = (uint32_t)((wm * 64 + mf * 16 + (lane & 15)) * 128 + (lane >> 4) * 16);
            rbA[mf] = rb; xA[mf] = (rb >> 3) & 0x70;
        }
        #pragma unroll
        for (int nf = 0; nf < 4; ++nf) {
            uint32_t rb = (uint32_t)((wn * 32 + nf * 8 + (l2 & 7)) * 128 + (l2 >> 3) * 16);
            rbB[nf] = rb; xB[nf] = (rb >> 3) & 0x70;
        }
    }

    __syncthreads();   // A visible; B stages 0,1 issued

    for (int idx = 0; idx < 64; ++idx) {
        const int kc = idx & 7;

        if (idx + 2 < 64) {
            const int nxt = idx + 2;
            const int pt2 = nxt >> 3, kc2 = nxt & 7;
            const char* srcB = (const char*)(g_protoNh + (size_t)(pt2 * 128) * D + kc2 * 64);
            uint32_t base = sbB + (uint32_t)(nxt & 3) * 16384u;
            #pragma unroll
            for (int i = 0; i < 4; ++i) {
                int v = tid + i * 256;
                int pr = v >> 3, slot = v & 7;
                CP_ASYNC16(base + SWZ((uint32_t)(pr * 128 + slot * 16)),
                           srcB + (size_t)pr * 1024 + slot * 16);
            }
            CP_COMMIT();
            CP_WAIT(2);
        } else {
            CP_WAIT(0);
        }
        __syncthreads();   // single barrier per tile (4-stage ring makes WAR safe)

        if (kc == 0) {
            #pragma unroll
            for (int mf = 0; mf < 4; ++mf)
                #pragma unroll
                for (int nf = 0; nf < 4; ++nf)
                    #pragma unroll
                    for (int q = 0; q < 4; ++q) acc[mf][nf][q] = 0.f;
        }

        const uint32_t aBase = sbA + (uint32_t)kc * 16384u;
        const uint32_t bBase = sbB + (uint32_t)(idx & 3) * 16384u;
        #pragma unroll
        for (int ks = 0; ks < 4; ++ks) {
            uint32_t af[4][4], bf[4][2];
            #pragma unroll
            for (int mf = 0; mf < 4; ++mf)
                ldsm_x4(af[mf], aBase + ((rbA[mf] + ks * 32) ^ xA[mf]));
            #pragma unroll
            for (int nf = 0; nf < 4; ++nf)
                ldsm_x2(bf[nf], bBase + ((rbB[nf] + ks * 32) ^ xB[nf]));
            #pragma unroll
            for (int mf = 0; mf < 4; ++mf)
                #pragma unroll
                for (int nf = 0; nf < 4; ++nf)
                    mma16816(acc[mf][nf], af[mf], bf[nf]);
        }

        if (kc == 7) {
            const int pt = idx >> 3;
            #pragma unroll
            for (int mf = 0; mf < 4; ++mf) {
                #pragma unroll
                for (int nf = 0; nf < 4; ++nf) {
                    int col = pt * 128 + wn * 32 + nf * 8 + (lane & 3) * 2;
                    FOLD(mf * 2 + 0, acc[mf][nf][0], col);
                    FOLD(mf * 2 + 0, acc[mf][nf][1], col + 1);
                    FOLD(mf * 2 + 1, acc[mf][nf][2], col);
                    FOLD(mf * 2 + 1, acc[mf][nf][3], col + 1);
                }
            }
        }
    }

    // ---- quad reduce (lanes with same lane/4 share rows, differ in cols) ----
    #pragma unroll
    for (int s = 0; s < 8; ++s) {
        #pragma unroll
        for (int off = 1; off <= 2; off <<= 1) {
            float ov1 = __shfl_xor_sync(0xffffffffu, tv1[s], off);
            int   oi1 = __shfl_xor_sync(0xffffffffu, ti1[s], off);
            float ov2 = __shfl_xor_sync(0xffffffffu, tv2[s], off);
            int   oi2 = __shfl_xor_sync(0xffffffffu, ti2[s], off);
            bool alead = (tv1[s] > ov1) || (tv1[s] == ov1 && ti1[s] < oi1);
            float nv1 = alead ? tv1[s] : ov1;  int ni1 = alead ? ti1[s] : oi1;
            float cv  = alead ? ov1 : tv1[s];  int ci  = alead ? oi1 : ti1[s];
            float sv  = alead ? tv2[s] : ov2;  int si  = alead ? ti2[s] : oi2;
            bool slead = (sv > cv) || (sv == cv && si < ci);
            tv1[s] = nv1; ti1[s] = ni1;
            tv2[s] = slead ? sv : cv; ti2[s] = slead ? si : ci;
        }
    }
    __syncthreads();   // done with B smem; reuse for cross-warp merge

    float4* buf = (float4*)(smem + 131072);
    if ((lane & 3) == 0) {
        #pragma unroll
        for (int mf = 0; mf < 4; ++mf)
            #pragma unroll
            for (int h = 0; h < 2; ++h) {
                int r = wm * 64 + mf * 16 + (lane >> 2) + h * 8;
                int s = mf * 2 + h;
                buf[wn * 128 + r] = make_float4(tv1[s], __int_as_float(ti1[s]),
                                                tv2[s], __int_as_float(ti2[s]));
            }
    }
    __syncthreads();

    if (tid < 128) {
        float4 m = buf[tid];
        float v1 = m.x; int i1 = __float_as_int(m.y);
        float v2 = m.z; int i2 = __float_as_int(m.w);
        #pragma unroll
        for (int w = 1; w < 4; ++w) {
            float4 o = buf[w * 128 + tid];
            float ov1 = o.x; int oi1 = __float_as_int(o.y);
            float ov2 = o.z; int oi2 = __float_as_int(o.w);
            bool alead = (v1 > ov1) || (v1 == ov1 && i1 < oi1);
            float nv1 = alead ? v1 : ov1;  int ni1 = alead ? i1 : oi1;
            float cv  = alead ? ov1 : v1;  int ci  = alead ? oi1 : i1;
            float sv  = alead ? v2 : ov2;  int si  = alead ? i2 : oi2;
            bool slead = (sv > cv) || (sv == cv && si < ci);
            v1 = nv1; i1 = ni1;
            v2 = slead ? sv : cv; i2 = slead ? si : ci;
        }
        int grow = row0 + tid;
        if (grow < n) {
            g_cand[grow * 2 + 0] = i1;
            g_cand[grow * 2 + 1] = i2;
        }
    }
}

// =====================================================================
// K3: fp32 rescoring of top-2 candidates + segment accumulation.
// =====================================================================
__global__ void k3_rescore_accum(const float* __restrict__ emb, int n) {
    int lane = threadIdx.x & 31;
    int row  = blockIdx.x * 8 + (threadIdx.x >> 5);
    if (row >= n) return;

    int i1 = g_cand[row * 2 + 0];
    int i2 = g_cand[row * 2 + 1];
    float inv = g_invn[row];

    const float4* e4 = (const float4*)(emb + (size_t)row * D);
    const float4* p1 = (const float4*)(g_protoN + (size_t)i1 * D);
    const float4* p2 = (const float4*)(g_protoN + (size_t)i2 * D);

    float4 ev[4];
    float s1 = 0.f, s2 = 0.f;
    #pragma unroll
    for (int q = 0; q < 4; ++q) {
        ev[q] = e4[q * 32 + lane];
        float4 a = p1[q * 32 + lane];
        float4 b = p2[q * 32 + lane];
        s1 += ev[q].x * a.x + ev[q].y * a.y + ev[q].z * a.z + ev[q].w * a.w;
        s2 += ev[q].x * b.x + ev[q].y * b.y + ev[q].z * b.z + ev[q].w * b.w;
    }
    #pragma unroll
    for (int o = 16; o; o >>= 1) {
        s1 += __shfl_xor_sync(0xffffffffu, s1, o);
        s2 += __shfl_xor_sync(0xffffffffu, s2, o);
    }
    int k = (s2 > s1 || (s2 == s1 && i2 < i1)) ? i2 : i1;

    float4* dst = (float4*)(g_sums + (size_t)k * D);
    #pragma unroll
    for (int q = 0; q < 4; ++q) {
        float4 v = ev[q];
        v.x *= inv; v.y *= inv; v.z *= inv; v.w *= inv;
        atomicAdd(&dst[q * 32 + lane], v);
    }
    if (lane == 0) atomicAdd(&g_counts[k], 1);
}

// =====================================================================
// K4: EMA + renormalize + where(has)
// =====================================================================
__global__ void k4_final(const float* __restrict__ protos, float* __restrict__ out) {
    int lane = threadIdx.x & 31;
    int k    = blockIdx.x * 8 + (threadIdx.x >> 5);
    if (k >= KPROT) return;

    int   cnt = g_counts[k];
    float cf  = fmaxf((float)cnt, 1.f);
    float pv[16], uv[16];
    float ss = 0.f;
    #pragma unroll
    for (int q = 0; q < 16; ++q) {
        pv[q] = protos[(size_t)k * D + lane + 32 * q];
        float m = g_sums[(size_t)k * D + lane + 32 * q] / cf;
        uv[q] = 0.9f * pv[q] + 0.1f * m;
        ss += uv[q] * uv[q];
    }
    #pragma unroll
    for (int o = 16; o; o >>= 1) ss += __shfl_xor_sync(0xffffffffu, ss, o);
    float inv = 1.f / fmaxf(sqrtf(ss), 1e-6f);
    #pragma unroll
    for (int q = 0; q < 16; ++q) {
        out[(size_t)k * D + lane + 32 * q] = (cnt > 0) ? uv[q] * inv : pv[q];
    }
}

// =====================================================================
extern "C" void kernel_launch(void* const* d_in, const int* in_sizes, int n_in,
                              void* d_out, int out_size) {
    const float* emb    = (const float*)d_in[0];
    const float* protos = (const float*)d_in[1];
    float* out = (float*)d_out;
    int n = in_sizes[0] / D;   // 131072

    const int smem2 = 131072 + 4 * 16384;  // 192 KB
    cudaFuncSetAttribute(k2_mma, cudaFuncAttributeMaxDynamicSharedMemorySize, smem2);

    k1_norm_proto<<<KPROT / 8, 256>>>(protos);
    k2_mma<<<(n + 127) / 128, 256, smem2>>>(emb, n);
    k3_rescore_accum<<<(n + 7) / 8, 256>>>(emb, n);
    k4_final<<<KPROT / 8, 256>>>(protos, out);
}

// round 5
// speedup vs baseline: 10.1968x; 1.1172x over previous
#include <cuda_runtime.h>
#include <cuda_bf16.h>
#include <cstdint>

#define D      512
#define KPROT  1024
#define NMAX   131072

// ---------------- device scratch ----------------
__device__ float         g_protoN [KPROT * D];     // normalized prototypes fp32 (rescoring)
__device__ __nv_bfloat16 g_protoNh[KPROT * D];     // normalized prototypes bf16 (GEMM)
__device__ float         g_sums   [KPROT * D];
__device__ int           g_counts [KPROT];
__device__ float         g_invn   [NMAX];
__device__ int           g_cand   [NMAX * 2];      // top-2 candidate protos per row

// ---------------- helpers ----------------
__device__ __forceinline__ uint32_t smem_u32(const void* p) {
    uint32_t a;
    asm("{ .reg .u64 t; cvta.to.shared.u64 t, %1; cvt.u32.u64 %0, t; }" : "=r"(a) : "l"(p));
    return a;
}
#define SWZ(x) ((x) ^ (((x) >> 3) & 0x70))

#define CP_ASYNC16(dst, src) \
    asm volatile("cp.async.cg.shared.global [%0], [%1], 16;" :: "r"(dst), "l"(src))
#define CP_COMMIT() asm volatile("cp.async.commit_group;")
#define CP_WAIT(n)  asm volatile("cp.async.wait_group %0;" :: "n"(n))

__device__ __forceinline__ void ldsm_x4(uint32_t a[4], uint32_t addr) {
    asm volatile("ldmatrix.sync.aligned.m8n8.x4.shared.b16 {%0,%1,%2,%3}, [%4];"
        : "=r"(a[0]), "=r"(a[1]), "=r"(a[2]), "=r"(a[3]) : "r"(addr));
}
__device__ __forceinline__ void mma16816(float c[4], const uint32_t a[4], const uint32_t b0, const uint32_t b1) {
    asm volatile(
        "mma.sync.aligned.m16n8k16.row.col.f32.bf16.bf16.f32 "
        "{%0,%1,%2,%3},{%4,%5,%6,%7},{%8,%9},{%0,%1,%2,%3};"
        : "+f"(c[0]), "+f"(c[1]), "+f"(c[2]), "+f"(c[3])
        : "r"(a[0]), "r"(a[1]), "r"(a[2]), "r"(a[3]), "r"(b0), "r"(b1));
}

// =====================================================================
// K1: normalize prototypes -> fp32 + bf16; zero sums/counts
// =====================================================================
__global__ void k1_norm_proto(const float* __restrict__ protos) {
    int lane = threadIdx.x & 31;
    int row  = blockIdx.x * 8 + (threadIdx.x >> 5);

    if (blockIdx.x < 4) g_counts[blockIdx.x * 256 + threadIdx.x] = 0;
    {
        float4* s4 = (float4*)g_sums;
        int t = blockIdx.x * 256 + threadIdx.x;
        #pragma unroll
        for (int q = 0; q < 4; ++q) s4[q * 32768 + t] = make_float4(0.f, 0.f, 0.f, 0.f);
    }

    const float4* src = (const float4*)(protos + (size_t)row * D);
    float4 v[4];
    float ss = 0.f;
    #pragma unroll
    for (int q = 0; q < 4; ++q) {
        v[q] = src[q * 32 + lane];
        ss += v[q].x * v[q].x + v[q].y * v[q].y + v[q].z * v[q].z + v[q].w * v[q].w;
    }
    #pragma unroll
    for (int o = 16; o; o >>= 1) ss += __shfl_xor_sync(0xffffffffu, ss, o);
    float inv = 1.f / fmaxf(sqrtf(ss), 1e-6f);

    float4* dstf = (float4*)(g_protoN + (size_t)row * D);
    uint2*  dsth = (uint2*)(g_protoNh + (size_t)row * D);
    #pragma unroll
    for (int q = 0; q < 4; ++q) {
        float4 w = make_float4(v[q].x * inv, v[q].y * inv, v[q].z * inv, v[q].w * inv);
        dstf[q * 32 + lane] = w;
        __nv_bfloat162 b0 = __floats2bfloat162_rn(w.x, w.y);
        __nv_bfloat162 b1 = __floats2bfloat162_rn(w.z, w.w);
        dsth[q * 32 + lane] = make_uint2(*(uint32_t*)&b0, *(uint32_t*)&b1);
    }
}

// =====================================================================
// K2: fused normalize + bf16 mma.sync GEMM [128 x 1024 x 512] per CTA
// + per-row top-2 candidates.
// 512 threads, 16 warps = 4(M) x 4(N); warp tile 32x32; 4 warps/SMSP.
// A: fp32 rows normalized in-kernel -> bf16 SW128 SMEM (128 KB).
// B: 4-stage 16 KB cp.async ring, distance-2 prefetch, 1 barrier/tile.
// =====================================================================
#define FOLD(slot, val, col) do { \
    float _v = (val); int _c = (col); \
    if (_v > tv1[slot]) { tv2[slot] = tv1[slot]; ti2[slot] = ti1[slot]; tv1[slot] = _v; ti1[slot] = _c; } \
    else if (_v > tv2[slot]) { tv2[slot] = _v; ti2[slot] = _c; } \
} while (0)

__global__ void __launch_bounds__(512, 1) k2_mma(const float* __restrict__ emb, int n) {
    extern __shared__ char smem[];
    const uint32_t sbA = smem_u32(smem);
    const uint32_t sbB = sbA + 131072;

    const int tid  = threadIdx.x;
    const int lane = tid & 31;
    const int wid  = tid >> 5;
    const int wm   = wid >> 2;   // 0..3 (32 rows each)
    const int wn   = wid & 3;    // 0..3 (32 cols each)
    const int row0 = blockIdx.x * 128;

    // ---- issue B stages 0,1 (tiles idx=0,1): 1024 x 16B each, 2/thread ----
    {
        const char* srcB0 = (const char*)g_protoNh;                 // pt=0,kc=0
        #pragma unroll
        for (int i = 0; i < 2; ++i) {
            int v = tid + i * 512;
            int pr = v >> 3, slot = v & 7;
            CP_ASYNC16(sbB + SWZ((uint32_t)(pr * 128 + slot * 16)),
                       srcB0 + (size_t)pr * 1024 + slot * 16);
        }
        CP_COMMIT();
        const char* srcB1 = (const char*)g_protoNh + 128;           // pt=0,kc=1
        #pragma unroll
        for (int i = 0; i < 2; ++i) {
            int v = tid + i * 512;
            int pr = v >> 3, slot = v & 7;
            CP_ASYNC16(sbB + 16384u + SWZ((uint32_t)(pr * 128 + slot * 16)),
                       srcB1 + (size_t)pr * 1024 + slot * 16);
        }
        CP_COMMIT();
    }

    // ---- A phase: load raw fp32, normalize, bf16 into SW128 smem ----
    // warp per row, 8 rows per warp. Lane l owns floats [16l, 16l+16).
    #pragma unroll 1
    for (int rr = 0; rr < 8; ++rr) {
        int r = wid * 8 + rr;
        int grow = row0 + r;
        const float4* src = (const float4*)(emb + (size_t)grow * D);
        float4 v[4];
        float ss = 0.f;
        if (grow < n) {
            #pragma unroll
            for (int q = 0; q < 4; ++q) {
                v[q] = src[lane * 4 + q];
                ss += v[q].x * v[q].x + v[q].y * v[q].y + v[q].z * v[q].z + v[q].w * v[q].w;
            }
        } else {
            #pragma unroll
            for (int q = 0; q < 4; ++q) v[q] = make_float4(0.f, 0.f, 0.f, 0.f);
        }
        #pragma unroll
        for (int o = 16; o; o >>= 1) ss += __shfl_xor_sync(0xffffffffu, ss, o);
        float inv = 1.f / fmaxf(sqrtf(ss), 1e-6f);
        if (lane == 0 && grow < n) g_invn[grow] = inv;

        uint32_t hb[8];
        #pragma unroll
        for (int q = 0; q < 4; ++q) {
            __nv_bfloat162 b0 = __floats2bfloat162_rn(v[q].x * inv, v[q].y * inv);
            __nv_bfloat162 b1 = __floats2bfloat162_rn(v[q].z * inv, v[q].w * inv);
            hb[q * 2 + 0] = *(uint32_t*)&b0;
            hb[q * 2 + 1] = *(uint32_t*)&b1;
        }
        #pragma unroll
        for (int h = 0; h < 2; ++h) {
            int s = lane * 2 + h;      // 16B slot 0..63 within row
            uint32_t off = (uint32_t)(s >> 3) * 16384u + SWZ((uint32_t)(r * 128 + (s & 7) * 16));
            *(uint4*)(smem + off) = make_uint4(hb[h * 4 + 0], hb[h * 4 + 1], hb[h * 4 + 2], hb[h * 4 + 3]);
        }
    }

    float acc[2][4][4];
    float tv1[4], tv2[4];
    int   ti1[4], ti2[4];
    #pragma unroll
    for (int s = 0; s < 4; ++s) { tv1[s] = -3.4e38f; tv2[s] = -3.4e38f; ti1[s] = 0; ti2[s] = 0; }

    // ldmatrix base byte offsets + constant swizzle XORs
    uint32_t rbA[2], xA[2], rbB[2], xB[2];
    {
        #pragma unroll
        for (int mf = 0; mf < 2; ++mf) {
            uint32_t rb = (uint32_t)((wm * 32 + mf * 16 + (lane & 15)) * 128 + (lane >> 4) * 16);
            rbA[mf] = rb; xA[mf] = (rb >> 3) & 0x70;
        }
        // B x4: two n-tiles of 8 per op. row = wn*32 + nh*16 + (lane>>4)*8 + (lane&7),
        // 16B slot = (lane>>3)&1.
        #pragma unroll
        for (int nh = 0; nh < 2; ++nh) {
            uint32_t rw = (uint32_t)(wn * 32 + nh * 16 + ((lane >> 4) << 3) + (lane & 7));
            uint32_t rb = rw * 128 + (((uint32_t)lane >> 3) & 1u) * 16u;
            rbB[nh] = rb; xB[nh] = (rb >> 3) & 0x70;
        }
    }

    __syncthreads();   // A visible; B stages 0,1 issued

    for (int idx = 0; idx < 64; ++idx) {
        const int kc = idx & 7;

        if (idx + 2 < 64) {
            const int nxt = idx + 2;
            const int pt2 = nxt >> 3, kc2 = nxt & 7;
            const char* srcB = (const char*)(g_protoNh + (size_t)(pt2 * 128) * D + kc2 * 64);
            uint32_t base = sbB + (uint32_t)(nxt & 3) * 16384u;
            #pragma unroll
            for (int i = 0; i < 2; ++i) {
                int v = tid + i * 512;
                int pr = v >> 3, slot = v & 7;
                CP_ASYNC16(base + SWZ((uint32_t)(pr * 128 + slot * 16)),
                           srcB + (size_t)pr * 1024 + slot * 16);
            }
            CP_COMMIT();
            CP_WAIT(2);
        } else {
            CP_WAIT(0);
        }
        __syncthreads();   // 4-stage ring makes WAR safe with one barrier

        if (kc == 0) {
            #pragma unroll
            for (int mf = 0; mf < 2; ++mf)
                #pragma unroll
                for (int nf = 0; nf < 4; ++nf)
                    #pragma unroll
                    for (int q = 0; q < 4; ++q) acc[mf][nf][q] = 0.f;
        }

        const uint32_t aBase = sbA + (uint32_t)kc * 16384u;
        const uint32_t bBase = sbB + (uint32_t)(idx & 3) * 16384u;
        #pragma unroll
        for (int ks = 0; ks < 4; ++ks) {
            uint32_t af[2][4], bf[2][4];
            #pragma unroll
            for (int mf = 0; mf < 2; ++mf)
                ldsm_x4(af[mf], aBase + ((rbA[mf] + ks * 32) ^ xA[mf]));
            #pragma unroll
            for (int nh = 0; nh < 2; ++nh)
                ldsm_x4(bf[nh], bBase + ((rbB[nh] + ks * 32) ^ xB[nh]));
            #pragma unroll
            for (int mf = 0; mf < 2; ++mf) {
                #pragma unroll
                for (int nh = 0; nh < 2; ++nh) {
                    mma16816(acc[mf][nh * 2 + 0], af[mf], bf[nh][0], bf[nh][1]);
                    mma16816(acc[mf][nh * 2 + 1], af[mf], bf[nh][2], bf[nh][3]);
                }
            }
        }

        if (kc == 7) {
            const int pt = idx >> 3;
            #pragma unroll
            for (int mf = 0; mf < 2; ++mf) {
                #pragma unroll
                for (int nf = 0; nf < 4; ++nf) {
                    int col = pt * 128 + wn * 32 + nf * 8 + (lane & 3) * 2;
                    FOLD(mf * 2 + 0, acc[mf][nf][0], col);
                    FOLD(mf * 2 + 0, acc[mf][nf][1], col + 1);
                    FOLD(mf * 2 + 1, acc[mf][nf][2], col);
                    FOLD(mf * 2 + 1, acc[mf][nf][3], col + 1);
                }
            }
        }
    }

    // ---- quad reduce (4 lanes per row share cols) ----
    #pragma unroll
    for (int s = 0; s < 4; ++s) {
        #pragma unroll
        for (int off = 1; off <= 2; off <<= 1) {
            float ov1 = __shfl_xor_sync(0xffffffffu, tv1[s], off);
            int   oi1 = __shfl_xor_sync(0xffffffffu, ti1[s], off);
            float ov2 = __shfl_xor_sync(0xffffffffu, tv2[s], off);
            int   oi2 = __shfl_xor_sync(0xffffffffu, ti2[s], off);
            bool alead = (tv1[s] > ov1) || (tv1[s] == ov1 && ti1[s] < oi1);
            float nv1 = alead ? tv1[s] : ov1;  int ni1 = alead ? ti1[s] : oi1;
            float cv  = alead ? ov1 : tv1[s];  int ci  = alead ? oi1 : ti1[s];
            float sv  = alead ? tv2[s] : ov2;  int si  = alead ? ti2[s] : oi2;
            bool slead = (sv > cv) || (sv == cv && si < ci);
            tv1[s] = nv1; ti1[s] = ni1;
            tv2[s] = slead ? sv : cv; ti2[s] = slead ? si : ci;
        }
    }
    __syncthreads();   // done with B smem; reuse for cross-warp merge

    float4* buf = (float4*)(smem + 131072);
    if ((lane & 3) == 0) {
        #pragma unroll
        for (int mf = 0; mf < 2; ++mf)
            #pragma unroll
            for (int h = 0; h < 2; ++h) {
                int r = wm * 32 + mf * 16 + (lane >> 2) + h * 8;
                int s = mf * 2 + h;
                buf[wn * 128 + r] = make_float4(tv1[s], __int_as_float(ti1[s]),
                                                tv2[s], __int_as_float(ti2[s]));
            }
    }
    __syncthreads();

    if (tid < 128) {
        float4 m = buf[tid];
        float v1 = m.x; int i1 = __float_as_int(m.y);
        float v2 = m.z; int i2 = __float_as_int(m.w);
        #pragma unroll
        for (int w = 1; w < 4; ++w) {
            float4 o = buf[w * 128 + tid];
            float ov1 = o.x; int oi1 = __float_as_int(o.y);
            float ov2 = o.z; int oi2 = __float_as_int(o.w);
            bool alead = (v1 > ov1) || (v1 == ov1 && i1 < oi1);
            float nv1 = alead ? v1 : ov1;  int ni1 = alead ? i1 : oi1;
            float cv  = alead ? ov1 : v1;  int ci  = alead ? oi1 : i1;
            float sv  = alead ? v2 : ov2;  int si  = alead ? i2 : oi2;
            bool slead = (sv > cv) || (sv == cv && si < ci);
            v1 = nv1; i1 = ni1;
            v2 = slead ? sv : cv; i2 = slead ? si : ci;
        }
        int grow = row0 + tid;
        if (grow < n) {
            g_cand[grow * 2 + 0] = i1;
            g_cand[grow * 2 + 1] = i2;
        }
    }
}

// =====================================================================
// K3: fp32 rescoring of top-2 candidates + segment accumulation.
// =====================================================================
__global__ void k3_rescore_accum(const float* __restrict__ emb, int n) {
    int lane = threadIdx.x & 31;
    int row  = blockIdx.x * 8 + (threadIdx.x >> 5);
    if (row >= n) return;

    int i1 = g_cand[row * 2 + 0];
    int i2 = g_cand[row * 2 + 1];
    float inv = g_invn[row];

    const float4* e4 = (const float4*)(emb + (size_t)row * D);
    const float4* p1 = (const float4*)(g_protoN + (size_t)i1 * D);
    const float4* p2 = (const float4*)(g_protoN + (size_t)i2 * D);

    float4 ev[4];
    float s1 = 0.f, s2 = 0.f;
    #pragma unroll
    for (int q = 0; q < 4; ++q) {
        ev[q] = e4[q * 32 + lane];
        float4 a = p1[q * 32 + lane];
        float4 b = p2[q * 32 + lane];
        s1 += ev[q].x * a.x + ev[q].y * a.y + ev[q].z * a.z + ev[q].w * a.w;
        s2 += ev[q].x * b.x + ev[q].y * b.y + ev[q].z * b.z + ev[q].w * b.w;
    }
    #pragma unroll
    for (int o = 16; o; o >>= 1) {
        s1 += __shfl_xor_sync(0xffffffffu, s1, o);
        s2 += __shfl_xor_sync(0xffffffffu, s2, o);
    }
    int k = (s2 > s1 || (s2 == s1 && i2 < i1)) ? i2 : i1;

    float4* dst = (float4*)(g_sums + (size_t)k * D);
    #pragma unroll
    for (int q = 0; q < 4; ++q) {
        float4 v = ev[q];
        v.x *= inv; v.y *= inv; v.z *= inv; v.w *= inv;
        atomicAdd(&dst[q * 32 + lane], v);
    }
    if (lane == 0) atomicAdd(&g_counts[k], 1);
}

// =====================================================================
// K4: EMA + renormalize + where(has)
// =====================================================================
__global__ void k4_final(const float* __restrict__ protos, float* __restrict__ out) {
    int lane = threadIdx.x & 31;
    int k    = blockIdx.x * 8 + (threadIdx.x >> 5);
    if (k >= KPROT) return;

    int   cnt = g_counts[k];
    float cf  = fmaxf((float)cnt, 1.f);
    float pv[16], uv[16];
    float ss = 0.f;
    #pragma unroll
    for (int q = 0; q < 16; ++q) {
        pv[q] = protos[(size_t)k * D + lane + 32 * q];
        float m = g_sums[(size_t)k * D + lane + 32 * q] / cf;
        uv[q] = 0.9f * pv[q] + 0.1f * m;
        ss += uv[q] * uv[q];
    }
    #pragma unroll
    for (int o = 16; o; o >>= 1) ss += __shfl_xor_sync(0xffffffffu, ss, o);
    float inv = 1.f / fmaxf(sqrtf(ss), 1e-6f);
    #pragma unroll
    for (int q = 0; q < 16; ++q) {
        out[(size_t)k * D + lane + 32 * q] = (cnt > 0) ? uv[q] * inv : pv[q];
    }
}

// =====================================================================
extern "C" void kernel_launch(void* const* d_in, const int* in_sizes, int n_in,
                              void* d_out, int out_size) {
    const float* emb    = (const float*)d_in[0];
    const float* protos = (const float*)d_in[1];
    float* out = (float*)d_out;
    int n = in_sizes[0] / D;   // 131072

    const int smem2 = 131072 + 4 * 16384;  // 192 KB
    cudaFuncSetAttribute(k2_mma, cudaFuncAttributeMaxDynamicSharedMemorySize, smem2);

    k1_norm_proto<<<KPROT / 8, 256>>>(protos);
    k2_mma<<<(n + 127) / 128, 512, smem2>>>(emb, n);
    k3_rescore_accum<<<(n + 7) / 8, 256>>>(emb, n);
    k4_final<<<KPROT / 8, 256>>>(protos, out);
}